// round 1
// baseline (speedup 1.0000x reference)
#include <cuda_runtime.h>
#include <cuda_bf16.h>
#include <math.h>

// ---------------------------------------------------------------------------
// Mamba block forward, fp32 SIMT baseline.
// Shapes: B=2, T=2048, D_MODEL=768, D_INNER=1536, D_STATE=16, D_CONV=4
// Inputs (metadata order):
//  0 x (2,2048,768) 1 in_W (3072,768) 2 in_b (3072) 3 conv_W (1536,1,4)
//  4 conv_b (1536)  5 xp_W (33,1536)  6 xp_b (33)   7 dp_W (1536,1)
//  8 dp_b (1536)    9 A_log (1536,16) 10 D (1536)   11 out_W (768,1536)
//  12 out_b (768)
// Output: (2,2048,768) fp32
// ---------------------------------------------------------------------------

#define BATCH   2
#define SEQ     2048
#define DMODEL  768
#define DINNER  1536
#define DSTATE  16
#define ROWS    (BATCH * SEQ)        // 4096

// scratch (static device globals: allowed; runtime allocs are not)
__device__ float d_xz  [(size_t)ROWS * 2 * DINNER];  // 4096 x 3072
__device__ float d_xact[(size_t)ROWS * DINNER];      // silu(conv(x_branch))
__device__ float d_bcd [(size_t)ROWS * 33];          // [B(16) C(16) delta_raw(1)]
__device__ float d_g   [(size_t)ROWS * DINNER];      // gated ssm output

// ---------------------------------------------------------------------------
// GEMM: C[M,N] = A[M,K] * B[N,K]^T + bias[N]   (both row-major, K contiguous)
// 128x128 tile, BK=8, 256 threads, 8x8 per-thread microtile.
// M % 128 == 0, N % 128 == 0, K % 8 == 0 guaranteed by shapes.
// ---------------------------------------------------------------------------
#define GBM 128
#define GBN 128
#define GBK 8

__global__ __launch_bounds__(256)
void gemm_nt_kernel(const float* __restrict__ A, const float* __restrict__ B,
                    const float* __restrict__ bias, float* __restrict__ C,
                    int M, int N, int K)
{
    __shared__ float As[GBK][GBM];
    __shared__ float Bs[GBK][GBN];

    const int bm = blockIdx.y * GBM;
    const int bn = blockIdx.x * GBN;
    const int tid = threadIdx.x;

    // loaders: 128 rows x 8 k per operand = 256 float4
    const int lr = tid >> 1;            // 0..127
    const int lk = (tid & 1) * 4;       // 0 or 4

    const int tx = tid & 15;            // 0..15 -> n
    const int ty = tid >> 4;            // 0..15 -> m

    const float* Aptr = A + (size_t)(bm + lr) * K + lk;
    const float* Bptr = B + (size_t)(bn + lr) * K + lk;

    float acc[8][8];
#pragma unroll
    for (int i = 0; i < 8; i++)
#pragma unroll
        for (int j = 0; j < 8; j++) acc[i][j] = 0.f;

    for (int k0 = 0; k0 < K; k0 += GBK) {
        float4 a4 = *(const float4*)(Aptr + k0);
        float4 b4 = *(const float4*)(Bptr + k0);
        As[lk + 0][lr] = a4.x; As[lk + 1][lr] = a4.y;
        As[lk + 2][lr] = a4.z; As[lk + 3][lr] = a4.w;
        Bs[lk + 0][lr] = b4.x; Bs[lk + 1][lr] = b4.y;
        Bs[lk + 2][lr] = b4.z; Bs[lk + 3][lr] = b4.w;
        __syncthreads();

#pragma unroll
        for (int kk = 0; kk < GBK; kk++) {
            float4 a0 = *(const float4*)&As[kk][ty * 8];
            float4 a1 = *(const float4*)&As[kk][ty * 8 + 4];
            float4 b0 = *(const float4*)&Bs[kk][tx * 8];
            float4 b1 = *(const float4*)&Bs[kk][tx * 8 + 4];
            float ar[8] = {a0.x, a0.y, a0.z, a0.w, a1.x, a1.y, a1.z, a1.w};
            float br[8] = {b0.x, b0.y, b0.z, b0.w, b1.x, b1.y, b1.z, b1.w};
#pragma unroll
            for (int i = 0; i < 8; i++)
#pragma unroll
                for (int j = 0; j < 8; j++)
                    acc[i][j] = fmaf(ar[i], br[j], acc[i][j]);
        }
        __syncthreads();
    }

#pragma unroll
    for (int i = 0; i < 8; i++) {
        const int m = bm + ty * 8 + i;
        float* crow = C + (size_t)m * N + bn + tx * 8;
#pragma unroll
        for (int j = 0; j < 8; j++)
            crow[j] = acc[i][j] + bias[bn + tx * 8 + j];
    }
}

// ---------------------------------------------------------------------------
// Depthwise causal conv (width 4) + SiLU over the x branch of xz.
// grid: (DINNER/256, SEQ/128, BATCH), block 256. Coalesced over d.
// ---------------------------------------------------------------------------
__global__ __launch_bounds__(256)
void conv_silu_kernel(const float* __restrict__ xz,
                      const float* __restrict__ convW,
                      const float* __restrict__ convb,
                      float* __restrict__ xact)
{
    const int d  = blockIdx.x * 256 + threadIdx.x;
    const int b  = blockIdx.z;
    const int t0 = blockIdx.y * 128;

    const float w0 = convW[d * 4 + 0];
    const float w1 = convW[d * 4 + 1];
    const float w2 = convW[d * 4 + 2];
    const float w3 = convW[d * 4 + 3];
    const float cb = convb[d];

    const float* base = xz + (size_t)b * SEQ * (2 * DINNER) + d;
    float xm3 = (t0 - 3 >= 0) ? base[(size_t)(t0 - 3) * (2 * DINNER)] : 0.f;
    float xm2 = (t0 - 2 >= 0) ? base[(size_t)(t0 - 2) * (2 * DINNER)] : 0.f;
    float xm1 = (t0 - 1 >= 0) ? base[(size_t)(t0 - 1) * (2 * DINNER)] : 0.f;

    float* obase = xact + (size_t)b * SEQ * DINNER + d;
#pragma unroll 4
    for (int t = t0; t < t0 + 128; t++) {
        float xc = base[(size_t)t * (2 * DINNER)];
        float v  = fmaf(w0, xm3, fmaf(w1, xm2, fmaf(w2, xm1, fmaf(w3, xc, cb))));
        obase[(size_t)t * DINNER] = v / (1.f + __expf(-v));   // silu
        xm3 = xm2; xm2 = xm1; xm1 = xc;
    }
}

// ---------------------------------------------------------------------------
// Small projection: bcd[row, 0..32] = xact[row,:] @ xp_W^T + xp_b
// Block handles 4 rows (smem-staged); warp w computes outputs n = w, w+4, ...
// ---------------------------------------------------------------------------
__global__ __launch_bounds__(128)
void xssm_kernel(const float* __restrict__ xact, const float* __restrict__ xpW,
                 const float* __restrict__ xpb, float* __restrict__ bcd)
{
    __shared__ float sx[4][DINNER];
    const int r0  = blockIdx.x * 4;
    const int tid = threadIdx.x;

    for (int r = 0; r < 4; r++)
        for (int i = tid; i < DINNER; i += 128)
            sx[r][i] = xact[(size_t)(r0 + r) * DINNER + i];
    __syncthreads();

    const int lane = tid & 31;
    const int w    = tid >> 5;

    for (int n = w; n < 33; n += 4) {
        const float* wr = xpW + (size_t)n * DINNER;
        float s0 = 0.f, s1 = 0.f, s2 = 0.f, s3 = 0.f;
        for (int k = lane; k < DINNER; k += 32) {
            float wv = wr[k];
            s0 = fmaf(sx[0][k], wv, s0);
            s1 = fmaf(sx[1][k], wv, s1);
            s2 = fmaf(sx[2][k], wv, s2);
            s3 = fmaf(sx[3][k], wv, s3);
        }
#pragma unroll
        for (int o = 16; o; o >>= 1) {
            s0 += __shfl_xor_sync(0xffffffffu, s0, o);
            s1 += __shfl_xor_sync(0xffffffffu, s1, o);
            s2 += __shfl_xor_sync(0xffffffffu, s2, o);
            s3 += __shfl_xor_sync(0xffffffffu, s3, o);
        }
        if (lane == 0) {
            float bv = xpb[n];
            bcd[(size_t)(r0 + 0) * 33 + n] = s0 + bv;
            bcd[(size_t)(r0 + 1) * 33 + n] = s1 + bv;
            bcd[(size_t)(r0 + 2) * 33 + n] = s2 + bv;
            bcd[(size_t)(r0 + 3) * 33 + n] = s3 + bv;
        }
    }
}

// ---------------------------------------------------------------------------
// Selective scan + gating.
// Block = 128 threads = 8 groups of 16 lanes; group -> one d channel,
// lane n in [0,16) -> one SSM state. Chunked smem staging (TS=64):
// delta=softplus(...) and silu(z) precomputed during staging so the inner
// step carries a single MUFU (exp(delta*A_n)).
// grid: (DINNER/8, BATCH)
// ---------------------------------------------------------------------------
#define TS 64

__global__ __launch_bounds__(128)
void scan_kernel(const float* __restrict__ xz, const float* __restrict__ xact,
                 const float* __restrict__ bcd, const float* __restrict__ dpW,
                 const float* __restrict__ dpb, const float* __restrict__ Alog,
                 const float* __restrict__ Dvec, float* __restrict__ g)
{
    __shared__ float sRaw[TS][36];       // [B(16) C(16) dr(1)] per t, padded
    __shared__ float sX[TS][8];          // silu'd conv x for the 8 d's
    __shared__ float sZs[TS][8];         // silu(z)
    __shared__ float sDelta[TS][8];      // softplus(dr*dpw+dpb) per (t,d)
    __shared__ float s_dpw[8], s_dpb[8];

    const int tid = threadIdx.x;
    const int grp = tid >> 4;            // 0..7
    const int n   = tid & 15;            // state index
    const int b   = blockIdx.y;
    const int d0  = blockIdx.x * 8;
    const int d   = d0 + grp;

    if (tid < 8) { s_dpw[tid] = dpW[d0 + tid]; s_dpb[tid] = dpb[d0 + tid]; }

    const float negA = -__expf(Alog[(size_t)d * DSTATE + n]);  // = -(n+1)
    const float Dd   = Dvec[d];
    const size_t rowbase = (size_t)b * SEQ;

    float h = 0.f;
    __syncthreads();

    for (int t0 = 0; t0 < SEQ; t0 += TS) {
        // ---- stage phase 1: raw bcd rows (coalesced), x, silu(z) ----
        const float* bb = bcd + (rowbase + t0) * 33;
        for (int i = tid; i < TS * 33; i += 128) {
            int tt = i / 33;
            sRaw[tt][i - tt * 33] = bb[i];
        }
        for (int i = tid; i < TS * 8; i += 128) {
            int tt = i >> 3, gg = i & 7;
            size_t row = rowbase + t0 + tt;
            sX[tt][gg] = xact[row * DINNER + d0 + gg];
            float zv = xz[row * (2 * DINNER) + DINNER + d0 + gg];
            sZs[tt][gg] = zv / (1.f + __expf(-zv));
        }
        __syncthreads();

        // ---- stage phase 2: delta = softplus(dr*dpw + dpb) ----
        for (int i = tid; i < TS * 8; i += 128) {
            int tt = i >> 3, gg = i & 7;
            float pre = fmaf(sRaw[tt][32], s_dpw[gg], s_dpb[gg]);
            sDelta[tt][gg] = (pre > 20.f) ? pre : log1pf(__expf(pre));
        }
        __syncthreads();

        // ---- recurrence ----
#pragma unroll 4
        for (int tt = 0; tt < TS; tt++) {
            float delta = sDelta[tt][grp];
            float a  = __expf(delta * negA);
            float xv = sX[tt][grp];
            h = fmaf(a, h, (delta * sRaw[tt][n]) * xv);     // Bbar*x
            float c = h * sRaw[tt][16 + n];                 // h * C_n
            c += __shfl_xor_sync(0xffffffffu, c, 8);
            c += __shfl_xor_sync(0xffffffffu, c, 4);
            c += __shfl_xor_sync(0xffffffffu, c, 2);
            c += __shfl_xor_sync(0xffffffffu, c, 1);
            if (n == 0) {
                g[(rowbase + t0 + tt) * DINNER + d] =
                    (c + xv * Dd) * sZs[tt][grp];
            }
        }
        __syncthreads();
    }
}

// ---------------------------------------------------------------------------
extern "C" void kernel_launch(void* const* d_in, const int* in_sizes, int n_in,
                              void* d_out, int out_size)
{
    const float* x      = (const float*)d_in[0];
    const float* in_W   = (const float*)d_in[1];
    const float* in_b   = (const float*)d_in[2];
    const float* conv_W = (const float*)d_in[3];
    const float* conv_b = (const float*)d_in[4];
    const float* xp_W   = (const float*)d_in[5];
    const float* xp_b   = (const float*)d_in[6];
    const float* dp_W   = (const float*)d_in[7];
    const float* dp_b   = (const float*)d_in[8];
    const float* A_log  = (const float*)d_in[9];
    const float* Dv     = (const float*)d_in[10];
    const float* out_W  = (const float*)d_in[11];
    const float* out_b  = (const float*)d_in[12];
    float* out          = (float*)d_out;

    float* xz   = nullptr;  cudaGetSymbolAddress((void**)&xz,   d_xz);
    float* xact = nullptr;  cudaGetSymbolAddress((void**)&xact, d_xact);
    float* bcd  = nullptr;  cudaGetSymbolAddress((void**)&bcd,  d_bcd);
    float* g    = nullptr;  cudaGetSymbolAddress((void**)&g,    d_g);

    // 1) xz = x @ in_W^T + in_b      (4096 x 3072, K=768)
    {
        dim3 grid((2 * DINNER) / GBN, ROWS / GBM);
        gemm_nt_kernel<<<grid, 256>>>(x, in_W, in_b, xz, ROWS, 2 * DINNER, DMODEL);
    }
    // 2) depthwise conv + silu on x branch
    {
        dim3 grid(DINNER / 256, SEQ / 128, BATCH);
        conv_silu_kernel<<<grid, 256>>>(xz, conv_W, conv_b, xact);
    }
    // 3) bcd = xact @ xp_W^T + xp_b  (4096 x 33, K=1536)
    {
        xssm_kernel<<<ROWS / 4, 128>>>(xact, xp_W, xp_b, bcd);
    }
    // 4) selective scan + gating -> g
    {
        dim3 grid(DINNER / 8, BATCH);
        scan_kernel<<<grid, 128>>>(xz, xact, bcd, dp_W, dp_b, A_log, Dv, g);
    }
    // 5) out = g @ out_W^T + out_b   (4096 x 768, K=1536)
    {
        dim3 grid(DMODEL / GBN, ROWS / GBM);
        gemm_nt_kernel<<<grid, 256>>>(g, out_W, out_b, out, ROWS, DMODEL, DINNER);
    }
}

// round 2
// speedup vs baseline: 1.5722x; 1.5722x over previous
#include <cuda_runtime.h>
#include <cuda_bf16.h>
#include <math.h>

// ---------------------------------------------------------------------------
// Mamba block forward. bf16x3 tensor-core GEMMs + chunked selective scan.
// Shapes: B=2, T=2048, D_MODEL=768, D_INNER=1536, D_STATE=16, D_CONV=4
// ---------------------------------------------------------------------------

#define BATCH   2
#define SEQ     2048
#define DMODEL  768
#define DINNER  1536
#define DSTATE  16
#define ROWS    (BATCH * SEQ)        // 4096
#define CH      8                    // scan chunks
#define CLEN    (SEQ / CH)           // 256

// scratch
__device__ float d_xz  [(size_t)ROWS * 2 * DINNER];
__device__ float d_xact[(size_t)ROWS * DINNER];
__device__ float d_bcd [(size_t)ROWS * 33];
__device__ float d_g   [(size_t)ROWS * DINNER];
__device__ float d_hfin [(size_t)BATCH * CH * DINNER * DSTATE];
__device__ float d_hinit[(size_t)BATCH * CH * DINNER * DSTATE];
__device__ float d_dsum [(size_t)BATCH * CH * DINNER];

// ---------------------------------------------------------------------------
// bf16x3 tensor-core GEMM: C[M,N] = A[M,K] @ B[N,K]^T + bias[N]
// fp32 in/out. Each fp32 value split to bf16 hi + bf16 lo(residual);
// acc += Ahi*Bhi + Ahi*Blo + Alo*Bhi  (fp32 accumulate).
// Block tile 128x128, BK=32, 256 threads = 8 warps (4m x 2n), warp tile 32x64.
// ---------------------------------------------------------------------------
#define TBM 128
#define TBN 128
#define TBK 32
#define SSTRIDE 20   // 32-bit units per row in smem (40 bf16, padded)

__device__ __forceinline__ void mma_bf16(float* c, const unsigned* a, const unsigned* b)
{
    asm volatile(
        "mma.sync.aligned.m16n8k16.row.col.f32.bf16.bf16.f32 "
        "{%0,%1,%2,%3}, {%4,%5,%6,%7}, {%8,%9}, {%0,%1,%2,%3};\n"
        : "+f"(c[0]), "+f"(c[1]), "+f"(c[2]), "+f"(c[3])
        : "r"(a[0]), "r"(a[1]), "r"(a[2]), "r"(a[3]), "r"(b[0]), "r"(b[1]));
}

__global__ __launch_bounds__(256)
void gemm_tc_kernel(const float* __restrict__ A, const float* __restrict__ B,
                    const float* __restrict__ bias, float* __restrict__ C,
                    int M, int N, int K)
{
    __shared__ unsigned sAhi[TBM * SSTRIDE];
    __shared__ unsigned sAlo[TBM * SSTRIDE];
    __shared__ unsigned sBhi[TBN * SSTRIDE];
    __shared__ unsigned sBlo[TBN * SSTRIDE];

    const int tid = threadIdx.x;
    const int bm = blockIdx.y * TBM;
    const int bn = blockIdx.x * TBN;

    const int lane = tid & 31;
    const int wid  = tid >> 5;
    const int gid  = lane >> 2;       // 0..7
    const int tig  = lane & 3;        // 0..3
    const int warpM = wid >> 1;       // 0..3  (m offset *32)
    const int warpN = wid & 1;        // 0..1  (n offset *64)

    // loader mapping: 32 rows x 8 k-chunks(float4) per pass, 4 passes
    const int tr  = tid >> 3;         // 0..31
    const int tkv = (tid & 7) * 4;    // 0,4,...,28

    float acc[2][8][4];
#pragma unroll
    for (int i = 0; i < 2; i++)
#pragma unroll
        for (int j = 0; j < 8; j++)
#pragma unroll
            for (int l = 0; l < 4; l++) acc[i][j][l] = 0.f;

    for (int k0 = 0; k0 < K; k0 += TBK) {
        // ---- load + split A and B tiles ----
#pragma unroll
        for (int rr = 0; rr < 4; rr++) {
            int row = rr * 32 + tr;
            float4 va = *(const float4*)(A + (size_t)(bm + row) * K + k0 + tkv);
            float4 vb = *(const float4*)(B + (size_t)(bn + row) * K + k0 + tkv);

            __nv_bfloat162 ah01 = __floats2bfloat162_rn(va.x, va.y);
            __nv_bfloat162 ah23 = __floats2bfloat162_rn(va.z, va.w);
            __nv_bfloat162 al01 = __floats2bfloat162_rn(
                va.x - __bfloat162float(ah01.x), va.y - __bfloat162float(ah01.y));
            __nv_bfloat162 al23 = __floats2bfloat162_rn(
                va.z - __bfloat162float(ah23.x), va.w - __bfloat162float(ah23.y));

            __nv_bfloat162 bh01 = __floats2bfloat162_rn(vb.x, vb.y);
            __nv_bfloat162 bh23 = __floats2bfloat162_rn(vb.z, vb.w);
            __nv_bfloat162 bl01 = __floats2bfloat162_rn(
                vb.x - __bfloat162float(bh01.x), vb.y - __bfloat162float(bh01.y));
            __nv_bfloat162 bl23 = __floats2bfloat162_rn(
                vb.z - __bfloat162float(bh23.x), vb.w - __bfloat162float(bh23.y));

            int si = row * SSTRIDE + (tkv >> 1);
            sAhi[si]     = *(unsigned*)&ah01;
            sAhi[si + 1] = *(unsigned*)&ah23;
            sAlo[si]     = *(unsigned*)&al01;
            sAlo[si + 1] = *(unsigned*)&al23;
            sBhi[si]     = *(unsigned*)&bh01;
            sBhi[si + 1] = *(unsigned*)&bh23;
            sBlo[si]     = *(unsigned*)&bl01;
            sBlo[si + 1] = *(unsigned*)&bl23;
        }
        __syncthreads();

        // ---- compute: 2 k16 steps ----
#pragma unroll
        for (int kk = 0; kk < 2; kk++) {
            unsigned ahi[2][4], alo[2][4];
#pragma unroll
            for (int mt = 0; mt < 2; mt++) {
                int r0 = warpM * 32 + mt * 16 + gid;
                int cb = kk * 8 + tig;              // 32-bit col
                ahi[mt][0] = sAhi[r0 * SSTRIDE + cb];
                ahi[mt][1] = sAhi[(r0 + 8) * SSTRIDE + cb];
                ahi[mt][2] = sAhi[r0 * SSTRIDE + cb + 4];
                ahi[mt][3] = sAhi[(r0 + 8) * SSTRIDE + cb + 4];
                alo[mt][0] = sAlo[r0 * SSTRIDE + cb];
                alo[mt][1] = sAlo[(r0 + 8) * SSTRIDE + cb];
                alo[mt][2] = sAlo[r0 * SSTRIDE + cb + 4];
                alo[mt][3] = sAlo[(r0 + 8) * SSTRIDE + cb + 4];
            }
#pragma unroll
            for (int nt = 0; nt < 8; nt++) {
                int nrow = warpN * 64 + nt * 8 + gid;
                int cb = kk * 8 + tig;
                unsigned bhi[2], blo[2];
                bhi[0] = sBhi[nrow * SSTRIDE + cb];
                bhi[1] = sBhi[nrow * SSTRIDE + cb + 4];
                blo[0] = sBlo[nrow * SSTRIDE + cb];
                blo[1] = sBlo[nrow * SSTRIDE + cb + 4];
#pragma unroll
                for (int mt = 0; mt < 2; mt++) {
                    mma_bf16(acc[mt][nt], alo[mt], bhi);
                    mma_bf16(acc[mt][nt], ahi[mt], blo);
                    mma_bf16(acc[mt][nt], ahi[mt], bhi);
                }
            }
        }
        __syncthreads();
    }

    // ---- epilogue ----
#pragma unroll
    for (int mt = 0; mt < 2; mt++) {
        int m0 = bm + warpM * 32 + mt * 16 + gid;
#pragma unroll
        for (int nt = 0; nt < 8; nt++) {
            int n0 = bn + warpN * 64 + nt * 8 + tig * 2;
            float b0 = bias[n0], b1 = bias[n0 + 1];
            float2 v0 = {acc[mt][nt][0] + b0, acc[mt][nt][1] + b1};
            float2 v1 = {acc[mt][nt][2] + b0, acc[mt][nt][3] + b1};
            *(float2*)(C + (size_t)m0 * N + n0) = v0;
            *(float2*)(C + (size_t)(m0 + 8) * N + n0) = v1;
        }
    }
}

// ---------------------------------------------------------------------------
// Depthwise causal conv (width 4) + SiLU.
// ---------------------------------------------------------------------------
__global__ __launch_bounds__(256)
void conv_silu_kernel(const float* __restrict__ xz,
                      const float* __restrict__ convW,
                      const float* __restrict__ convb,
                      float* __restrict__ xact)
{
    const int d  = blockIdx.x * 256 + threadIdx.x;
    const int b  = blockIdx.z;
    const int t0 = blockIdx.y * 128;

    const float w0 = convW[d * 4 + 0];
    const float w1 = convW[d * 4 + 1];
    const float w2 = convW[d * 4 + 2];
    const float w3 = convW[d * 4 + 3];
    const float cb = convb[d];

    const float* base = xz + (size_t)b * SEQ * (2 * DINNER) + d;
    float xm3 = (t0 - 3 >= 0) ? base[(size_t)(t0 - 3) * (2 * DINNER)] : 0.f;
    float xm2 = (t0 - 2 >= 0) ? base[(size_t)(t0 - 2) * (2 * DINNER)] : 0.f;
    float xm1 = (t0 - 1 >= 0) ? base[(size_t)(t0 - 1) * (2 * DINNER)] : 0.f;

    float* obase = xact + (size_t)b * SEQ * DINNER + d;
#pragma unroll 4
    for (int t = t0; t < t0 + 128; t++) {
        float xc = base[(size_t)t * (2 * DINNER)];
        float v  = fmaf(w0, xm3, fmaf(w1, xm2, fmaf(w2, xm1, fmaf(w3, xc, cb))));
        obase[(size_t)t * DINNER] = v / (1.f + __expf(-v));
        xm3 = xm2; xm2 = xm1; xm1 = xc;
    }
}

// ---------------------------------------------------------------------------
// bcd[row, 0..32] = xact[row,:] @ xp_W^T + xp_b
// ---------------------------------------------------------------------------
__global__ __launch_bounds__(128)
void xssm_kernel(const float* __restrict__ xact, const float* __restrict__ xpW,
                 const float* __restrict__ xpb, float* __restrict__ bcd)
{
    __shared__ float sx[4][DINNER];
    const int r0  = blockIdx.x * 4;
    const int tid = threadIdx.x;

    for (int r = 0; r < 4; r++)
        for (int i = tid; i < DINNER; i += 128)
            sx[r][i] = xact[(size_t)(r0 + r) * DINNER + i];
    __syncthreads();

    const int lane = tid & 31;
    const int w    = tid >> 5;

    for (int n = w; n < 33; n += 4) {
        const float* wr = xpW + (size_t)n * DINNER;
        float s0 = 0.f, s1 = 0.f, s2 = 0.f, s3 = 0.f;
        for (int k = lane; k < DINNER; k += 32) {
            float wv = wr[k];
            s0 = fmaf(sx[0][k], wv, s0);
            s1 = fmaf(sx[1][k], wv, s1);
            s2 = fmaf(sx[2][k], wv, s2);
            s3 = fmaf(sx[3][k], wv, s3);
        }
#pragma unroll
        for (int o = 16; o; o >>= 1) {
            s0 += __shfl_xor_sync(0xffffffffu, s0, o);
            s1 += __shfl_xor_sync(0xffffffffu, s1, o);
            s2 += __shfl_xor_sync(0xffffffffu, s2, o);
            s3 += __shfl_xor_sync(0xffffffffu, s3, o);
        }
        if (lane == 0) {
            float bv = xpb[n];
            bcd[(size_t)(r0 + 0) * 33 + n] = s0 + bv;
            bcd[(size_t)(r0 + 1) * 33 + n] = s1 + bv;
            bcd[(size_t)(r0 + 2) * 33 + n] = s2 + bv;
            bcd[(size_t)(r0 + 3) * 33 + n] = s3 + bv;
        }
    }
}

// ---------------------------------------------------------------------------
// Chunked selective scan.
// Pass A: per-chunk recurrence from h=0 -> chunk-final h, sum(delta).
// Pass B: serial combine over chunks -> exact chunk-initial states.
// Pass C: per-chunk recurrence from h_init with output + gating.
// ---------------------------------------------------------------------------
#define TS 64

__global__ __launch_bounds__(128)
void scan_partial_kernel(const float* __restrict__ xact,
                         const float* __restrict__ bcd,
                         const float* __restrict__ dpW,
                         const float* __restrict__ dpb,
                         const float* __restrict__ Alog,
                         float* __restrict__ hfin, float* __restrict__ dsum)
{
    __shared__ float sRaw[TS][36];
    __shared__ float sX[TS][8];
    __shared__ float sDelta[TS][8];
    __shared__ float s_dpw[8], s_dpb[8];

    const int tid = threadIdx.x;
    const int grp = tid >> 4;
    const int n   = tid & 15;
    const int b   = blockIdx.y;
    const int c   = blockIdx.z;
    const int d0  = blockIdx.x * 8;
    const int d   = d0 + grp;

    if (tid < 8) { s_dpw[tid] = dpW[d0 + tid]; s_dpb[tid] = dpb[d0 + tid]; }

    const float negA = -__expf(Alog[(size_t)d * DSTATE + n]);
    const size_t rowbase = (size_t)b * SEQ + (size_t)c * CLEN;

    float h = 0.f, ds = 0.f;
    __syncthreads();

    for (int t0 = 0; t0 < CLEN; t0 += TS) {
        const float* bb = bcd + (rowbase + t0) * 33;
        for (int i = tid; i < TS * 33; i += 128) {
            int tt = i / 33;
            sRaw[tt][i - tt * 33] = bb[i];
        }
        for (int i = tid; i < TS * 8; i += 128) {
            int tt = i >> 3, gg = i & 7;
            sX[tt][gg] = xact[(rowbase + t0 + tt) * DINNER + d0 + gg];
        }
        __syncthreads();
        for (int i = tid; i < TS * 8; i += 128) {
            int tt = i >> 3, gg = i & 7;
            float pre = fmaf(sRaw[tt][32], s_dpw[gg], s_dpb[gg]);
            sDelta[tt][gg] = (pre > 20.f) ? pre : log1pf(__expf(pre));
        }
        __syncthreads();
#pragma unroll 4
        for (int tt = 0; tt < TS; tt++) {
            float delta = sDelta[tt][grp];
            float a  = __expf(delta * negA);
            h = fmaf(a, h, (delta * sRaw[tt][n]) * sX[tt][grp]);
            ds += delta;
        }
        __syncthreads();
    }

    size_t base = ((size_t)b * CH + c) * DINNER + d;
    hfin[base * DSTATE + n] = h;
    if (n == 0) dsum[base] = ds;
}

__global__ __launch_bounds__(256)
void scan_combine_kernel(const float* __restrict__ Alog,
                         const float* __restrict__ hfin,
                         const float* __restrict__ dsum,
                         float* __restrict__ hinit)
{
    int idx = blockIdx.x * 256 + threadIdx.x;     // < BATCH*DINNER*16
    int n = idx & 15;
    int d = (idx >> 4) % DINNER;
    int b = idx / (DINNER * DSTATE);
    float negA = -__expf(Alog[(size_t)d * DSTATE + n]);
    float hi = 0.f;
    for (int c = 0; c < CH; c++) {
        size_t base = ((size_t)b * CH + c) * DINNER + d;
        hinit[base * DSTATE + n] = hi;
        float P = __expf(negA * dsum[base]);
        hi = fmaf(P, hi, hfin[base * DSTATE + n]);
    }
}

__global__ __launch_bounds__(128)
void scan_final_kernel(const float* __restrict__ xz,
                       const float* __restrict__ xact,
                       const float* __restrict__ bcd,
                       const float* __restrict__ dpW,
                       const float* __restrict__ dpb,
                       const float* __restrict__ Alog,
                       const float* __restrict__ Dvec,
                       const float* __restrict__ hinit,
                       float* __restrict__ g)
{
    __shared__ float sRaw[TS][36];
    __shared__ float sX[TS][8];
    __shared__ float sZs[TS][8];
    __shared__ float sDelta[TS][8];
    __shared__ float s_dpw[8], s_dpb[8];

    const int tid = threadIdx.x;
    const int grp = tid >> 4;
    const int n   = tid & 15;
    const int b   = blockIdx.y;
    const int c   = blockIdx.z;
    const int d0  = blockIdx.x * 8;
    const int d   = d0 + grp;

    if (tid < 8) { s_dpw[tid] = dpW[d0 + tid]; s_dpb[tid] = dpb[d0 + tid]; }

    const float negA = -__expf(Alog[(size_t)d * DSTATE + n]);
    const float Dd   = Dvec[d];
    const size_t rowbase = (size_t)b * SEQ + (size_t)c * CLEN;

    float h = hinit[(((size_t)b * CH + c) * DINNER + d) * DSTATE + n];
    __syncthreads();

    for (int t0 = 0; t0 < CLEN; t0 += TS) {
        const float* bb = bcd + (rowbase + t0) * 33;
        for (int i = tid; i < TS * 33; i += 128) {
            int tt = i / 33;
            sRaw[tt][i - tt * 33] = bb[i];
        }
        for (int i = tid; i < TS * 8; i += 128) {
            int tt = i >> 3, gg = i & 7;
            size_t row = rowbase + t0 + tt;
            sX[tt][gg] = xact[row * DINNER + d0 + gg];
            float zv = xz[row * (2 * DINNER) + DINNER + d0 + gg];
            sZs[tt][gg] = zv / (1.f + __expf(-zv));
        }
        __syncthreads();
        for (int i = tid; i < TS * 8; i += 128) {
            int tt = i >> 3, gg = i & 7;
            float pre = fmaf(sRaw[tt][32], s_dpw[gg], s_dpb[gg]);
            sDelta[tt][gg] = (pre > 20.f) ? pre : log1pf(__expf(pre));
        }
        __syncthreads();
#pragma unroll 4
        for (int tt = 0; tt < TS; tt++) {
            float delta = sDelta[tt][grp];
            float a  = __expf(delta * negA);
            float xv = sX[tt][grp];
            h = fmaf(a, h, (delta * sRaw[tt][n]) * xv);
            float cc = h * sRaw[tt][16 + n];
            cc += __shfl_xor_sync(0xffffffffu, cc, 8);
            cc += __shfl_xor_sync(0xffffffffu, cc, 4);
            cc += __shfl_xor_sync(0xffffffffu, cc, 2);
            cc += __shfl_xor_sync(0xffffffffu, cc, 1);
            if (n == 0) {
                g[(rowbase + t0 + tt) * DINNER + d] =
                    (cc + xv * Dd) * sZs[tt][grp];
            }
        }
        __syncthreads();
    }
}

// ---------------------------------------------------------------------------
extern "C" void kernel_launch(void* const* d_in, const int* in_sizes, int n_in,
                              void* d_out, int out_size)
{
    const float* x      = (const float*)d_in[0];
    const float* in_W   = (const float*)d_in[1];
    const float* in_b   = (const float*)d_in[2];
    const float* conv_W = (const float*)d_in[3];
    const float* conv_b = (const float*)d_in[4];
    const float* xp_W   = (const float*)d_in[5];
    const float* xp_b   = (const float*)d_in[6];
    const float* dp_W   = (const float*)d_in[7];
    const float* dp_b   = (const float*)d_in[8];
    const float* A_log  = (const float*)d_in[9];
    const float* Dv     = (const float*)d_in[10];
    const float* out_W  = (const float*)d_in[11];
    const float* out_b  = (const float*)d_in[12];
    float* out          = (float*)d_out;

    float *xz, *xact, *bcd, *g, *hfin, *hinit, *dsum;
    cudaGetSymbolAddress((void**)&xz,    d_xz);
    cudaGetSymbolAddress((void**)&xact,  d_xact);
    cudaGetSymbolAddress((void**)&bcd,   d_bcd);
    cudaGetSymbolAddress((void**)&g,     d_g);
    cudaGetSymbolAddress((void**)&hfin,  d_hfin);
    cudaGetSymbolAddress((void**)&hinit, d_hinit);
    cudaGetSymbolAddress((void**)&dsum,  d_dsum);

    // 1) xz = x @ in_W^T + in_b      (4096 x 3072, K=768)
    {
        dim3 grid((2 * DINNER) / TBN, ROWS / TBM);
        gemm_tc_kernel<<<grid, 256>>>(x, in_W, in_b, xz, ROWS, 2 * DINNER, DMODEL);
    }
    // 2) depthwise conv + silu
    {
        dim3 grid(DINNER / 256, SEQ / 128, BATCH);
        conv_silu_kernel<<<grid, 256>>>(xz, conv_W, conv_b, xact);
    }
    // 3) bcd = xact @ xp_W^T + xp_b
    {
        xssm_kernel<<<ROWS / 4, 128>>>(xact, xp_W, xp_b, bcd);
    }
    // 4) chunked selective scan
    {
        dim3 grid(DINNER / 8, BATCH, CH);
        scan_partial_kernel<<<grid, 128>>>(xact, bcd, dp_W, dp_b, A_log, hfin, dsum);
        scan_combine_kernel<<<(BATCH * DINNER * DSTATE) / 256, 256>>>(A_log, hfin, dsum, hinit);
        scan_final_kernel<<<grid, 128>>>(xz, xact, bcd, dp_W, dp_b, A_log, Dv, hinit, g);
    }
    // 5) out = g @ out_W^T + out_b   (4096 x 768, K=1536)
    {
        dim3 grid(DMODEL / TBN, ROWS / TBM);
        gemm_tc_kernel<<<grid, 256>>>(g, out_W, out_b, out, ROWS, DMODEL, DINNER);
    }
}